// round 6
// baseline (speedup 1.0000x reference)
#include <cuda_runtime.h>
#include <cuda_bf16.h>
#include <cstdint>

#define DH 64
#define BM 64            // q-rows per CTA (128 threads, 4 warps x 16 rows)
#define BN 64
#define SKB 144          // smem row stride bytes (72 bf16) -> ldmatrix conflict-free

#define SM_QHI 0
#define SM_QLO (SM_QHI + BM*SKB)
#define SM_KHI (SM_QLO + BM*SKB)
#define SM_KLO (SM_KHI + BN*SKB)
#define SM_VHI (SM_KLO + BN*SKB)
#define SM_VLO (SM_VHI + BN*SKB)
#define SM_TOTAL (SM_VLO + BN*SKB)   // 55296 B -> 2 CTAs/SM

#define MAXROWS 16384                 // B*Lq capacity of scratch
#define NCH_MAX 4

// split-KV scratch: unnormalized O partials + l partials (static device arrays)
__device__ float g_Opart[(size_t)NCH_MAX * MAXROWS * DH];
__device__ float g_lpart[(size_t)NCH_MAX * MAXROWS];

static __device__ __forceinline__ uint32_t smem_u32(const void* p){
    uint32_t a;
    asm("{ .reg .u64 t; cvta.to.shared.u64 t, %1; cvt.u32.u64 %0, t; }" : "=r"(a) : "l"(p));
    return a;
}
static __device__ __forceinline__ uint32_t pk(__nv_bfloat16 a, __nv_bfloat16 b){
    __nv_bfloat162 t; t.x = a; t.y = b;
    return *reinterpret_cast<uint32_t*>(&t);
}
static __device__ __forceinline__ void split8(const float* f, uint4& hi, uint4& lo){
    uint32_t h[4], l[4];
    #pragma unroll
    for (int i = 0; i < 4; i++){
        __nv_bfloat16 h0 = __float2bfloat16(f[2*i]);
        __nv_bfloat16 h1 = __float2bfloat16(f[2*i+1]);
        __nv_bfloat16 l0 = __float2bfloat16(f[2*i]   - __bfloat162float(h0));
        __nv_bfloat16 l1 = __float2bfloat16(f[2*i+1] - __bfloat162float(h1));
        h[i] = pk(h0, h1); l[i] = pk(l0, l1);
    }
    hi = make_uint4(h[0], h[1], h[2], h[3]);
    lo = make_uint4(l[0], l[1], l[2], l[3]);
}
static __device__ __forceinline__ void ldsm4(uint32_t* r, uint32_t a){
    asm volatile("ldmatrix.sync.aligned.m8n8.x4.shared.b16 {%0,%1,%2,%3}, [%4];"
                 : "=r"(r[0]), "=r"(r[1]), "=r"(r[2]), "=r"(r[3]) : "r"(a));
}
static __device__ __forceinline__ void ldsm4t(uint32_t* r, uint32_t a){
    asm volatile("ldmatrix.sync.aligned.m8n8.x4.trans.shared.b16 {%0,%1,%2,%3}, [%4];"
                 : "=r"(r[0]), "=r"(r[1]), "=r"(r[2]), "=r"(r[3]) : "r"(a));
}
static __device__ __forceinline__ void mma16816(float* d, const uint32_t* a, uint32_t b0, uint32_t b1){
    asm volatile("mma.sync.aligned.m16n8k16.row.col.f32.bf16.bf16.f32 "
                 "{%0,%1,%2,%3}, {%4,%5,%6,%7}, {%8,%9}, {%0,%1,%2,%3};"
                 : "+f"(d[0]), "+f"(d[1]), "+f"(d[2]), "+f"(d[3])
                 : "r"(a[0]), "r"(a[1]), "r"(a[2]), "r"(a[3]), "r"(b0), "r"(b1));
}

// ---------------- Phase 1: partial attention over one key chunk ----------------
__global__ __launch_bounds__(128, 2)
void fa_part_kernel(const float* __restrict__ Q, const float* __restrict__ K,
                    const float* __restrict__ V, const int* __restrict__ vlen,
                    int Lq, int Lk, int ck)
{
    extern __shared__ char smem[];
    const uint32_t sb = smem_u32(smem);
    const int t  = threadIdx.x;
    const int w  = t >> 5;
    const int ln = t & 31;
    const int g  = ln >> 2;
    const int tg = ln & 3;
    const int b  = blockIdx.y;
    const int q0 = blockIdx.x * BM;
    const int c  = blockIdx.z;

    int vl = vlen[b];
    if (vl < 1) vl = 1;
    if (vl > Lk) vl = Lk;

    const int cstart = c * ck;
    if (cstart >= vl) return;                       // empty chunk
    const int kend   = (cstart + ck < vl) ? cstart + ck : vl;
    const int ntiles = (kend - cstart + BN - 1) / BN;

    const int B_ = gridDim.y;
    const int R  = B_ * Lq;

    const float* Qb = Q + ((size_t)b * Lq + q0) * DH;
    const float* Kb = K + ((size_t)b * Lk + cstart) * DH;
    const float* Vb = V + ((size_t)b * Lk + cstart) * DH;

    // ---- Q -> smem, pre-scaled, bf16 hi/lo split (128 threads: r 0..63) ----
    {
        int r = t >> 1, h = t & 1;
        const float* qp = Qb + (size_t)r * DH + h * 32;
        float f[32];
        #pragma unroll
        for (int i = 0; i < 8; i++) *(float4*)(f + 4*i) = *(const float4*)(qp + 4*i);
        #pragma unroll
        for (int i = 0; i < 32; i++) f[i] *= 0.125f;   // 1/sqrt(64)
        #pragma unroll
        for (int cc = 0; cc < 4; cc++){
            uint4 hi, lo; split8(f + 8*cc, hi, lo);
            int off = r * SKB + (h*4 + cc) * 16;
            *(uint4*)(smem + SM_QHI + off) = hi;
            *(uint4*)(smem + SM_QLO + off) = lo;
        }
    }
    __syncthreads();

    // ---- Q A-fragments ----
    uint32_t qhi[4][4], qlo[4][4];
    {
        uint32_t rowoff = (uint32_t)(16*w + (ln & 15)) * SKB + (uint32_t)(ln >> 4) * 16;
        #pragma unroll
        for (int ks = 0; ks < 4; ks++){
            ldsm4(qhi[ks], sb + SM_QHI + rowoff + ks * 32);
            ldsm4(qlo[ks], sb + SM_QLO + rowoff + ks * 32);
        }
    }

    float oc[8][4];
    #pragma unroll
    for (int nt = 0; nt < 8; nt++)
        #pragma unroll
        for (int j = 0; j < 4; j++) oc[nt][j] = 0.f;
    float lsum0 = 0.f, lsum1 = 0.f;

    // ---- prefetch tile 0 (half-row per thread: 32 floats K + 32 floats V) ----
    const int r2 = t >> 1, hh = (t & 1) * 32;
    float4 kf[8], vf[8];
    {
        const float* kp = Kb + (size_t)r2 * DH + hh;
        const float* vp = Vb + (size_t)r2 * DH + hh;
        #pragma unroll
        for (int i = 0; i < 8; i++){ kf[i] = *(const float4*)(kp + 4*i); vf[i] = *(const float4*)(vp + 4*i); }
    }

    for (int kt = 0; kt < ntiles; kt++){
        const int n0g = cstart + kt * BN;           // global key offset of this tile

        __syncthreads();
        {
            int off = r2 * SKB + (hh >> 3) * 16;    // hh*2 bytes
            float fk[8];
            #pragma unroll
            for (int h2 = 0; h2 < 2; h2++){
                *(float4*)(fk)     = kf[4*h2 + 0]; *(float4*)(fk + 4) = kf[4*h2 + 1];
                uint4 hi, lo; split8(fk, hi, lo);
                *(uint4*)(smem + SM_KHI + off + 32*h2) = hi;
                *(uint4*)(smem + SM_KLO + off + 32*h2) = lo;
                *(float4*)(fk)     = kf[4*h2 + 2]; *(float4*)(fk + 4) = kf[4*h2 + 3];
                split8(fk, hi, lo);
                *(uint4*)(smem + SM_KHI + off + 32*h2 + 16) = hi;
                *(uint4*)(smem + SM_KLO + off + 32*h2 + 16) = lo;

                *(float4*)(fk)     = vf[4*h2 + 0]; *(float4*)(fk + 4) = vf[4*h2 + 1];
                split8(fk, hi, lo);
                *(uint4*)(smem + SM_VHI + off + 32*h2) = hi;
                *(uint4*)(smem + SM_VLO + off + 32*h2) = lo;
                *(float4*)(fk)     = vf[4*h2 + 2]; *(float4*)(fk + 4) = vf[4*h2 + 3];
                split8(fk, hi, lo);
                *(uint4*)(smem + SM_VHI + off + 32*h2 + 16) = hi;
                *(uint4*)(smem + SM_VLO + off + 32*h2 + 16) = lo;
            }
        }
        __syncthreads();

        // ---- prefetch next tile ----
        if (kt + 1 < ntiles){
            const float* kp = Kb + (size_t)((kt+1)*BN + r2) * DH + hh;
            const float* vp = Vb + (size_t)((kt+1)*BN + r2) * DH + hh;
            #pragma unroll
            for (int i = 0; i < 8; i++){ kf[i] = *(const float4*)(kp + 4*i); vf[i] = *(const float4*)(vp + 4*i); }
        }

        // ---- S = Q K^T (split precision, 3 passes) ----
        float sc[8][4];
        #pragma unroll
        for (int nt = 0; nt < 8; nt++){
            #pragma unroll
            for (int j = 0; j < 4; j++) sc[nt][j] = 0.f;
            uint32_t kh[8], kl[8];
            uint32_t base = (uint32_t)(8*nt + (ln & 7)) * SKB
                          + (uint32_t)((ln >> 3) & 1) * 16
                          + (uint32_t)(ln >> 4) * 32;
            ldsm4(kh + 0, sb + SM_KHI + base);
            ldsm4(kh + 4, sb + SM_KHI + base + 64);
            ldsm4(kl + 0, sb + SM_KLO + base);
            ldsm4(kl + 4, sb + SM_KLO + base + 64);
            #pragma unroll
            for (int ks = 0; ks < 4; ks++){
                mma16816(sc[nt], qhi[ks], kh[2*ks], kh[2*ks+1]);
                mma16816(sc[nt], qhi[ks], kl[2*ks], kl[2*ks+1]);
                mma16816(sc[nt], qlo[ks], kh[2*ks], kh[2*ks+1]);
            }
        }

        // ---- P = exp(S) with key-length mask ----
        uint32_t phi[4][4], plo[4][4];
        #pragma unroll
        for (int nt = 0; nt < 8; nt++){
            int c0 = n0g + nt*8 + 2*tg;
            float e0 = (c0     < vl) ? __expf(sc[nt][0]) : 0.f;
            float e1 = (c0 + 1 < vl) ? __expf(sc[nt][1]) : 0.f;
            float e2 = (c0     < vl) ? __expf(sc[nt][2]) : 0.f;
            float e3 = (c0 + 1 < vl) ? __expf(sc[nt][3]) : 0.f;
            lsum0 += e0 + e1;
            lsum1 += e2 + e3;
            __nv_bfloat16 h0 = __float2bfloat16(e0), h1 = __float2bfloat16(e1);
            __nv_bfloat16 h2 = __float2bfloat16(e2), h3 = __float2bfloat16(e3);
            __nv_bfloat16 x0 = __float2bfloat16(e0 - __bfloat162float(h0));
            __nv_bfloat16 x1 = __float2bfloat16(e1 - __bfloat162float(h1));
            __nv_bfloat16 x2 = __float2bfloat16(e2 - __bfloat162float(h2));
            __nv_bfloat16 x3 = __float2bfloat16(e3 - __bfloat162float(h3));
            int j = nt >> 1, hf = (nt & 1) * 2;
            phi[j][hf + 0] = pk(h0, h1); phi[j][hf + 1] = pk(h2, h3);
            plo[j][hf + 0] = pk(x0, x1); plo[j][hf + 1] = pk(x2, x3);
        }

        // ---- O += P V (split precision, 3 passes) ----
        #pragma unroll
        for (int nt = 0; nt < 8; nt++){
            uint32_t vh[8], vr[8];
            uint32_t base = (uint32_t)ln * SKB + (uint32_t)nt * 16;
            ldsm4t(vh + 0, sb + SM_VHI + base);
            ldsm4t(vh + 4, sb + SM_VHI + base + 32u * SKB);
            ldsm4t(vr + 0, sb + SM_VLO + base);
            ldsm4t(vr + 4, sb + SM_VLO + base + 32u * SKB);
            #pragma unroll
            for (int ks = 0; ks < 4; ks++){
                mma16816(oc[nt], phi[ks], vh[2*ks], vh[2*ks+1]);
                mma16816(oc[nt], phi[ks], vr[2*ks], vr[2*ks+1]);
                mma16816(oc[nt], plo[ks], vh[2*ks], vh[2*ks+1]);
            }
        }
    }

    // ---- reduce row sums across quads ----
    lsum0 += __shfl_xor_sync(0xffffffffu, lsum0, 1);
    lsum0 += __shfl_xor_sync(0xffffffffu, lsum0, 2);
    lsum1 += __shfl_xor_sync(0xffffffffu, lsum1, 1);
    lsum1 += __shfl_xor_sync(0xffffffffu, lsum1, 2);

    // ---- write unnormalized partials to scratch ----
    const int rg0 = b * Lq + q0 + 16*w + g;         // global row
    float* Op0 = g_Opart + ((size_t)c * R + rg0) * DH;
    float* Op1 = Op0 + (size_t)8 * DH;
    if (tg == 0){
        g_lpart[(size_t)c * R + rg0]     = lsum0;
        g_lpart[(size_t)c * R + rg0 + 8] = lsum1;
    }
    #pragma unroll
    for (int nt = 0; nt < 8; nt++){
        float2 a0, a1;
        a0.x = oc[nt][0]; a0.y = oc[nt][1];
        a1.x = oc[nt][2]; a1.y = oc[nt][3];
        *(float2*)(Op0 + nt*8 + 2*tg) = a0;
        *(float2*)(Op1 + nt*8 + 2*tg) = a1;
    }
}

// ---------------- Phase 2: combine chunk partials + normalize ----------------
__global__ __launch_bounds__(256, 8)
void fa_combine_kernel(const int* __restrict__ vlen, float* __restrict__ O,
                       int Lq, int Lk, int B, int ck)
{
    const int idx = blockIdx.x * blockDim.x + threadIdx.x;
    const int total = B * Lq * (DH / 4);
    if (idx >= total) return;

    const int rd = idx >> 4;        // global row (b*Lq + q)
    const int d4 = idx & 15;
    const int b  = rd / Lq;
    const int R  = B * Lq;

    int vl = vlen[b];
    if (vl < 1) vl = 1;
    if (vl > Lk) vl = Lk;
    const int nact = (vl + ck - 1) / ck;

    // unconditional loads (static scratch always addressable) -> MLP=4,
    // then predicated select. Stale slots are masked out, never used.
    float4 p[NCH_MAX];
    float  lp[NCH_MAX];
    #pragma unroll
    for (int c = 0; c < NCH_MAX; c++){
        p[c]  = *(const float4*)(g_Opart + ((size_t)c * R + rd) * DH + d4 * 4);
        lp[c] = g_lpart[(size_t)c * R + rd];
    }
    float4 acc = make_float4(0.f, 0.f, 0.f, 0.f);
    float l = 0.f;
    #pragma unroll
    for (int c = 0; c < NCH_MAX; c++){
        const bool v = (c < nact);
        acc.x += v ? p[c].x : 0.f;
        acc.y += v ? p[c].y : 0.f;
        acc.z += v ? p[c].z : 0.f;
        acc.w += v ? p[c].w : 0.f;
        l     += v ? lp[c]  : 0.f;
    }
    const float inv = 1.f / l;
    acc.x *= inv; acc.y *= inv; acc.z *= inv; acc.w *= inv;
    *(float4*)(O + (size_t)rd * DH + d4 * 4) = acc;
}

extern "C" void kernel_launch(void* const* d_in, const int* in_sizes, int n_in,
                              void* d_out, int out_size)
{
    const float* Q  = (const float*)d_in[0];
    const float* K  = (const float*)d_in[1];
    const float* V  = (const float*)d_in[2];
    const int*   vl = (const int*)d_in[3];
    float*       O  = (float*)d_out;

    const int B  = in_sizes[3];
    const int Lq = in_sizes[0] / (B * DH);
    const int Lk = in_sizes[1] / (B * DH);

    // chunk size: multiple of BN, at most NCH_MAX chunks
    int ck = ((Lk + NCH_MAX * BN - 1) / (NCH_MAX * BN)) * BN;
    if (ck < BN) ck = BN;
    const int nch = (Lk + ck - 1) / ck;

    cudaFuncSetAttribute(fa_part_kernel,
                         cudaFuncAttributeMaxDynamicSharedMemorySize, SM_TOTAL);

    dim3 grid1(Lq / BM, B, nch);
    fa_part_kernel<<<grid1, 128, SM_TOTAL>>>(Q, K, V, vl, Lq, Lk, ck);

    const int total = B * Lq * (DH / 4);
    fa_combine_kernel<<<(total + 255) / 256, 256>>>(vl, O, Lq, Lk, B, ck);
}

// round 7
// speedup vs baseline: 1.2314x; 1.2314x over previous
#include <cuda_runtime.h>
#include <cuda_bf16.h>
#include <cstdint>

#define DH 64
#define BM 128
#define BN 64
#define SKB 144          // smem row stride bytes (72 bf16) -> ldmatrix conflict-free

// Q (single) + double-buffered K/V
#define SM_QHI 0
#define SM_QLO (BM*SKB)               // 18432
#define SM_BUF (2*BM*SKB)             // 36864 : start of buffer 0
#define BUFSTRIDE (4*BN*SKB)          // 36864 : KHI,KLO,VHI,VLO per buffer
#define OF_KHI 0
#define OF_KLO (BN*SKB)
#define OF_VHI (2*BN*SKB)
#define OF_VLO (3*BN*SKB)
#define SM_TOTAL (SM_BUF + 2*BUFSTRIDE)   // 110592 B

#define MAXROWS 16384
#define NCH_MAX 4

__device__ float g_Opart[(size_t)NCH_MAX * MAXROWS * DH];
__device__ float g_lpart[(size_t)NCH_MAX * MAXROWS];

static __device__ __forceinline__ uint32_t smem_u32(const void* p){
    uint32_t a;
    asm("{ .reg .u64 t; cvta.to.shared.u64 t, %1; cvt.u32.u64 %0, t; }" : "=r"(a) : "l"(p));
    return a;
}
static __device__ __forceinline__ uint32_t pk(__nv_bfloat16 a, __nv_bfloat16 b){
    __nv_bfloat162 t; t.x = a; t.y = b;
    return *reinterpret_cast<uint32_t*>(&t);
}
static __device__ __forceinline__ void split8(const float* f, uint4& hi, uint4& lo){
    uint32_t h[4], l[4];
    #pragma unroll
    for (int i = 0; i < 4; i++){
        __nv_bfloat16 h0 = __float2bfloat16(f[2*i]);
        __nv_bfloat16 h1 = __float2bfloat16(f[2*i+1]);
        __nv_bfloat16 l0 = __float2bfloat16(f[2*i]   - __bfloat162float(h0));
        __nv_bfloat16 l1 = __float2bfloat16(f[2*i+1] - __bfloat162float(h1));
        h[i] = pk(h0, h1); l[i] = pk(l0, l1);
    }
    hi = make_uint4(h[0], h[1], h[2], h[3]);
    lo = make_uint4(l[0], l[1], l[2], l[3]);
}
static __device__ __forceinline__ void ldsm4(uint32_t* r, uint32_t a){
    asm volatile("ldmatrix.sync.aligned.m8n8.x4.shared.b16 {%0,%1,%2,%3}, [%4];"
                 : "=r"(r[0]), "=r"(r[1]), "=r"(r[2]), "=r"(r[3]) : "r"(a));
}
static __device__ __forceinline__ void ldsm4t(uint32_t* r, uint32_t a){
    asm volatile("ldmatrix.sync.aligned.m8n8.x4.trans.shared.b16 {%0,%1,%2,%3}, [%4];"
                 : "=r"(r[0]), "=r"(r[1]), "=r"(r[2]), "=r"(r[3]) : "r"(a));
}
static __device__ __forceinline__ void mma16816(float* d, const uint32_t* a, uint32_t b0, uint32_t b1){
    asm volatile("mma.sync.aligned.m16n8k16.row.col.f32.bf16.bf16.f32 "
                 "{%0,%1,%2,%3}, {%4,%5,%6,%7}, {%8,%9}, {%0,%1,%2,%3};"
                 : "+f"(d[0]), "+f"(d[1]), "+f"(d[2]), "+f"(d[3])
                 : "r"(a[0]), "r"(a[1]), "r"(a[2]), "r"(a[3]), "r"(b0), "r"(b1));
}

// convert one K/V tile (held in regs) to split bf16 and store into buffer `bb`
static __device__ __forceinline__ void conv_store(char* smem, int bb,
                                                  const float4* kf, const float4* vf,
                                                  int r4, int qq){
    int off = r4 * SKB + qq * 32;
    float fk[8];
    uint4 hi, lo;
    *(float4*)(fk)   = kf[0]; *(float4*)(fk+4) = kf[1];
    split8(fk, hi, lo);
    *(uint4*)(smem + bb + OF_KHI + off) = hi; *(uint4*)(smem + bb + OF_KLO + off) = lo;
    *(float4*)(fk)   = kf[2]; *(float4*)(fk+4) = kf[3];
    split8(fk, hi, lo);
    *(uint4*)(smem + bb + OF_KHI + off + 16) = hi; *(uint4*)(smem + bb + OF_KLO + off + 16) = lo;
    *(float4*)(fk)   = vf[0]; *(float4*)(fk+4) = vf[1];
    split8(fk, hi, lo);
    *(uint4*)(smem + bb + OF_VHI + off) = hi; *(uint4*)(smem + bb + OF_VLO + off) = lo;
    *(float4*)(fk)   = vf[2]; *(float4*)(fk+4) = vf[3];
    split8(fk, hi, lo);
    *(uint4*)(smem + bb + OF_VHI + off + 16) = hi; *(uint4*)(smem + bb + OF_VLO + off + 16) = lo;
}

// ---------------- Phase 1: partial attention over one key chunk ----------------
__global__ __launch_bounds__(256, 1)
void fa_part_kernel(const float* __restrict__ Q, const float* __restrict__ K,
                    const float* __restrict__ V, const int* __restrict__ vlen,
                    int Lq, int Lk, int ck)
{
    extern __shared__ char smem[];
    const uint32_t sb = smem_u32(smem);
    const int t  = threadIdx.x;
    const int w  = t >> 5;
    const int ln = t & 31;
    const int g  = ln >> 2;
    const int tg = ln & 3;
    const int b  = blockIdx.y;
    const int q0 = blockIdx.x * BM;
    const int c  = blockIdx.z;

    int vl = vlen[b];
    if (vl < 1) vl = 1;
    if (vl > Lk) vl = Lk;

    const int cstart = c * ck;
    if (cstart >= vl) return;
    const int kend   = (cstart + ck < vl) ? cstart + ck : vl;
    const int ntiles = (kend - cstart + BN - 1) / BN;

    const int B_ = gridDim.y;
    const int R  = B_ * Lq;

    const float* Qb = Q + ((size_t)b * Lq + q0) * DH;
    const float* Kb = K + ((size_t)b * Lk + cstart) * DH;
    const float* Vb = V + ((size_t)b * Lk + cstart) * DH;

    // ---- Q -> smem, pre-scaled, bf16 hi/lo split ----
    {
        int r = t >> 1, h = t & 1;
        const float* qp = Qb + (size_t)r * DH + h * 32;
        float f[32];
        #pragma unroll
        for (int i = 0; i < 8; i++) *(float4*)(f + 4*i) = *(const float4*)(qp + 4*i);
        #pragma unroll
        for (int i = 0; i < 32; i++) f[i] *= 0.125f;
        #pragma unroll
        for (int cc = 0; cc < 4; cc++){
            uint4 hi, lo; split8(f + 8*cc, hi, lo);
            int off = r * SKB + (h*4 + cc) * 16;
            *(uint4*)(smem + SM_QHI + off) = hi;
            *(uint4*)(smem + SM_QLO + off) = lo;
        }
    }

    // ---- prefetch tile 0 + store into buffer 0 ----
    const int r4 = t >> 2, qq = t & 3;
    float4 kf[4], vf[4];
    {
        const float* kp = Kb + (size_t)r4 * DH + qq * 16;
        const float* vp = Vb + (size_t)r4 * DH + qq * 16;
        #pragma unroll
        for (int i = 0; i < 4; i++){ kf[i] = *(const float4*)(kp + 4*i); vf[i] = *(const float4*)(vp + 4*i); }
    }
    conv_store(smem, SM_BUF, kf, vf, r4, qq);
    __syncthreads();

    // ---- Q A-fragments ----
    uint32_t qhi[4][4], qlo[4][4];
    {
        uint32_t rowoff = (uint32_t)(16*w + (ln & 15)) * SKB + (uint32_t)(ln >> 4) * 16;
        #pragma unroll
        for (int ks = 0; ks < 4; ks++){
            ldsm4(qhi[ks], sb + SM_QHI + rowoff + ks * 32);
            ldsm4(qlo[ks], sb + SM_QLO + rowoff + ks * 32);
        }
    }

    float oc[8][4];
    #pragma unroll
    for (int nt = 0; nt < 8; nt++)
        #pragma unroll
        for (int j = 0; j < 4; j++) oc[nt][j] = 0.f;
    float lsum0 = 0.f, lsum1 = 0.f;

    for (int kt = 0; kt < ntiles; kt++){
        const int n0g = cstart + kt * BN;
        const int cur = SM_BUF + (kt & 1) * BUFSTRIDE;
        const int nxt = SM_BUF + ((kt & 1) ^ 1) * BUFSTRIDE;
        const bool havenext = (kt + 1 < ntiles);

        // ---- prefetch next tile (LDG issued early, consumed by conv_store) ----
        if (havenext){
            const float* kp = Kb + (size_t)((kt+1)*BN + r4) * DH + qq * 16;
            const float* vp = Vb + (size_t)((kt+1)*BN + r4) * DH + qq * 16;
            #pragma unroll
            for (int i = 0; i < 4; i++){ kf[i] = *(const float4*)(kp + 4*i); vf[i] = *(const float4*)(vp + 4*i); }
        }

        // ---- S = Q K^T (split precision, 3 passes) ----
        float sc[8][4];
        #pragma unroll
        for (int nt = 0; nt < 8; nt++){
            #pragma unroll
            for (int j = 0; j < 4; j++) sc[nt][j] = 0.f;
            uint32_t kh[8], kl[8];
            uint32_t base = (uint32_t)(8*nt + (ln & 7)) * SKB
                          + (uint32_t)((ln >> 3) & 1) * 16
                          + (uint32_t)(ln >> 4) * 32;
            ldsm4(kh + 0, sb + cur + OF_KHI + base);
            ldsm4(kh + 4, sb + cur + OF_KHI + base + 64);
            ldsm4(kl + 0, sb + cur + OF_KLO + base);
            ldsm4(kl + 4, sb + cur + OF_KLO + base + 64);
            #pragma unroll
            for (int ks = 0; ks < 4; ks++){
                mma16816(sc[nt], qhi[ks], kh[2*ks], kh[2*ks+1]);
                mma16816(sc[nt], qhi[ks], kl[2*ks], kl[2*ks+1]);
                mma16816(sc[nt], qlo[ks], kh[2*ks], kh[2*ks+1]);
            }
        }

        // ---- convert next tile into other buffer (in the S-MMA shadow) ----
        if (havenext) conv_store(smem, nxt, kf, vf, r4, qq);

        // ---- P = exp(S) with key-length mask ----
        uint32_t phi[4][4], plo[4][4];
        #pragma unroll
        for (int nt = 0; nt < 8; nt++){
            int c0 = n0g + nt*8 + 2*tg;
            float e0 = (c0     < vl) ? __expf(sc[nt][0]) : 0.f;
            float e1 = (c0 + 1 < vl) ? __expf(sc[nt][1]) : 0.f;
            float e2 = (c0     < vl) ? __expf(sc[nt][2]) : 0.f;
            float e3 = (c0 + 1 < vl) ? __expf(sc[nt][3]) : 0.f;
            lsum0 += e0 + e1;
            lsum1 += e2 + e3;
            __nv_bfloat16 h0 = __float2bfloat16(e0), h1 = __float2bfloat16(e1);
            __nv_bfloat16 h2 = __float2bfloat16(e2), h3 = __float2bfloat16(e3);
            __nv_bfloat16 x0 = __float2bfloat16(e0 - __bfloat162float(h0));
            __nv_bfloat16 x1 = __float2bfloat16(e1 - __bfloat162float(h1));
            __nv_bfloat16 x2 = __float2bfloat16(e2 - __bfloat162float(h2));
            __nv_bfloat16 x3 = __float2bfloat16(e3 - __bfloat162float(h3));
            int j = nt >> 1, hf = (nt & 1) * 2;
            phi[j][hf + 0] = pk(h0, h1); phi[j][hf + 1] = pk(h2, h3);
            plo[j][hf + 0] = pk(x0, x1); plo[j][hf + 1] = pk(x2, x3);
        }

        // ---- O += P V (split precision, 3 passes) ----
        #pragma unroll
        for (int nt = 0; nt < 8; nt++){
            uint32_t vh[8], vr[8];
            uint32_t base = (uint32_t)ln * SKB + (uint32_t)nt * 16;
            ldsm4t(vh + 0, sb + cur + OF_VHI + base);
            ldsm4t(vh + 4, sb + cur + OF_VHI + base + 32u * SKB);
            ldsm4t(vr + 0, sb + cur + OF_VLO + base);
            ldsm4t(vr + 4, sb + cur + OF_VLO + base + 32u * SKB);
            #pragma unroll
            for (int ks = 0; ks < 4; ks++){
                mma16816(oc[nt], phi[ks], vh[2*ks], vh[2*ks+1]);
                mma16816(oc[nt], phi[ks], vr[2*ks], vr[2*ks+1]);
                mma16816(oc[nt], plo[ks], vh[2*ks], vh[2*ks+1]);
            }
        }

        __syncthreads();   // buffer turnover: writes of nxt visible, reads of cur done
    }

    // ---- reduce row sums across quads ----
    lsum0 += __shfl_xor_sync(0xffffffffu, lsum0, 1);
    lsum0 += __shfl_xor_sync(0xffffffffu, lsum0, 2);
    lsum1 += __shfl_xor_sync(0xffffffffu, lsum1, 1);
    lsum1 += __shfl_xor_sync(0xffffffffu, lsum1, 2);

    // ---- write unnormalized partials to scratch ----
    const int rg0 = b * Lq + q0 + 16*w + g;
    float* Op0 = g_Opart + ((size_t)c * R + rg0) * DH;
    float* Op1 = Op0 + (size_t)8 * DH;
    if (tg == 0){
        g_lpart[(size_t)c * R + rg0]     = lsum0;
        g_lpart[(size_t)c * R + rg0 + 8] = lsum1;
    }
    #pragma unroll
    for (int nt = 0; nt < 8; nt++){
        float2 a0, a1;
        a0.x = oc[nt][0]; a0.y = oc[nt][1];
        a1.x = oc[nt][2]; a1.y = oc[nt][3];
        *(float2*)(Op0 + nt*8 + 2*tg) = a0;
        *(float2*)(Op1 + nt*8 + 2*tg) = a1;
    }
}

// ---------------- Phase 2: combine chunk partials + normalize ----------------
__global__ __launch_bounds__(256, 8)
void fa_combine_kernel(const int* __restrict__ vlen, float* __restrict__ O,
                       int Lq, int Lk, int B, int ck)
{
    const int idx = blockIdx.x * blockDim.x + threadIdx.x;
    const int total = B * Lq * (DH / 4);
    if (idx >= total) return;

    const int rd = idx >> 4;
    const int d4 = idx & 15;
    const int b  = rd / Lq;
    const int R  = B * Lq;

    int vl = vlen[b];
    if (vl < 1) vl = 1;
    if (vl > Lk) vl = Lk;
    const int nact = (vl + ck - 1) / ck;

    float4 p[NCH_MAX];
    float  lp[NCH_MAX];
    #pragma unroll
    for (int c = 0; c < NCH_MAX; c++){
        p[c]  = *(const float4*)(g_Opart + ((size_t)c * R + rd) * DH + d4 * 4);
        lp[c] = g_lpart[(size_t)c * R + rd];
    }
    float4 acc = make_float4(0.f, 0.f, 0.f, 0.f);
    float l = 0.f;
    #pragma unroll
    for (int c = 0; c < NCH_MAX; c++){
        const bool v = (c < nact);
        acc.x += v ? p[c].x : 0.f;
        acc.y += v ? p[c].y : 0.f;
        acc.z += v ? p[c].z : 0.f;
        acc.w += v ? p[c].w : 0.f;
        l     += v ? lp[c]  : 0.f;
    }
    const float inv = 1.f / l;
    acc.x *= inv; acc.y *= inv; acc.z *= inv; acc.w *= inv;
    *(float4*)(O + (size_t)rd * DH + d4 * 4) = acc;
}

extern "C" void kernel_launch(void* const* d_in, const int* in_sizes, int n_in,
                              void* d_out, int out_size)
{
    const float* Q  = (const float*)d_in[0];
    const float* K  = (const float*)d_in[1];
    const float* V  = (const float*)d_in[2];
    const int*   vl = (const int*)d_in[3];
    float*       O  = (float*)d_out;

    const int B  = in_sizes[3];
    const int Lq = in_sizes[0] / (B * DH);
    const int Lk = in_sizes[1] / (B * DH);

    int ck = ((Lk + NCH_MAX * BN - 1) / (NCH_MAX * BN)) * BN;
    if (ck < BN) ck = BN;
    const int nch = (Lk + ck - 1) / ck;

    cudaFuncSetAttribute(fa_part_kernel,
                         cudaFuncAttributeMaxDynamicSharedMemorySize, SM_TOTAL);

    dim3 grid1(Lq / BM, B, nch);
    fa_part_kernel<<<grid1, 256, SM_TOTAL>>>(Q, K, V, vl, Lq, Lk, ck);

    const int total = B * Lq * (DH / 4);
    fa_combine_kernel<<<(total + 255) / 256, 256>>>(vl, O, Lq, Lk, B, ck);
}

// round 8
// speedup vs baseline: 1.7712x; 1.4383x over previous
#include <cuda_runtime.h>
#include <cuda_fp16.h>
#include <cstdint>

#define DH 64
#define BM 128
#define BN 64
#define SKB 144          // smem row stride bytes (72 fp16) -> ldmatrix conflict-free

#define SM_QHI 0
#define SM_QLO (BM*SKB)               // 18432
#define SM_KH  (2*BM*SKB)             // 36864
#define SM_VH  (SM_KH + BN*SKB)       // 46080
#define SM_TOTAL (SM_VH + BN*SKB)     // 55296 B

#define MAXROWS 16384
#define NCH_MAX 4

__device__ float g_Opart[(size_t)NCH_MAX * MAXROWS * DH];
__device__ float g_lpart[(size_t)NCH_MAX * MAXROWS];

static __device__ __forceinline__ uint32_t smem_u32(const void* p){
    uint32_t a;
    asm("{ .reg .u64 t; cvta.to.shared.u64 t, %1; cvt.u32.u64 %0, t; }" : "=r"(a) : "l"(p));
    return a;
}
static __device__ __forceinline__ uint32_t pkh(__half a, __half b){
    __half2 t = __halves2half2(a, b);
    return *reinterpret_cast<uint32_t*>(&t);
}
// 8 floats -> 8 fp16 (single precision-truncated copy)
static __device__ __forceinline__ void cvtH8(const float* f, uint4& out){
    uint32_t r[4];
    #pragma unroll
    for (int i = 0; i < 4; i++){
        __half2 h = __floats2half2_rn(f[2*i], f[2*i+1]);
        r[i] = *reinterpret_cast<uint32_t*>(&h);
    }
    out = make_uint4(r[0], r[1], r[2], r[3]);
}
// 8 floats -> hi/lo fp16 split (hi = rn(f), lo = rn(f - hi))
static __device__ __forceinline__ void splitH8(const float* f, uint4& hi, uint4& lo){
    uint32_t h[4], l[4];
    #pragma unroll
    for (int i = 0; i < 4; i++){
        __half h0 = __float2half_rn(f[2*i]);
        __half h1 = __float2half_rn(f[2*i+1]);
        __half l0 = __float2half_rn(f[2*i]   - __half2float(h0));
        __half l1 = __float2half_rn(f[2*i+1] - __half2float(h1));
        h[i] = pkh(h0, h1); l[i] = pkh(l0, l1);
    }
    hi = make_uint4(h[0], h[1], h[2], h[3]);
    lo = make_uint4(l[0], l[1], l[2], l[3]);
}
static __device__ __forceinline__ void ldsm4(uint32_t* r, uint32_t a){
    asm volatile("ldmatrix.sync.aligned.m8n8.x4.shared.b16 {%0,%1,%2,%3}, [%4];"
                 : "=r"(r[0]), "=r"(r[1]), "=r"(r[2]), "=r"(r[3]) : "r"(a));
}
static __device__ __forceinline__ void ldsm4t(uint32_t* r, uint32_t a){
    asm volatile("ldmatrix.sync.aligned.m8n8.x4.trans.shared.b16 {%0,%1,%2,%3}, [%4];"
                 : "=r"(r[0]), "=r"(r[1]), "=r"(r[2]), "=r"(r[3]) : "r"(a));
}
static __device__ __forceinline__ void mma16816(float* d, const uint32_t* a, uint32_t b0, uint32_t b1){
    asm volatile("mma.sync.aligned.m16n8k16.row.col.f32.f16.f16.f32 "
                 "{%0,%1,%2,%3}, {%4,%5,%6,%7}, {%8,%9}, {%0,%1,%2,%3};"
                 : "+f"(d[0]), "+f"(d[1]), "+f"(d[2]), "+f"(d[3])
                 : "r"(a[0]), "r"(a[1]), "r"(a[2]), "r"(a[3]), "r"(b0), "r"(b1));
}

// ---------------- Phase 1: partial attention over one key chunk ----------------
__global__ __launch_bounds__(256, 1)
void fa_part_kernel(const float* __restrict__ Q, const float* __restrict__ K,
                    const float* __restrict__ V, const int* __restrict__ vlen,
                    int Lq, int Lk, int ck)
{
    extern __shared__ char smem[];
    const uint32_t sb = smem_u32(smem);
    const int t  = threadIdx.x;
    const int w  = t >> 5;
    const int ln = t & 31;
    const int g  = ln >> 2;
    const int tg = ln & 3;
    const int b  = blockIdx.y;
    const int q0 = blockIdx.x * BM;
    const int c  = blockIdx.z;

    int vl = vlen[b];
    if (vl < 1) vl = 1;
    if (vl > Lk) vl = Lk;

    const int cstart = c * ck;
    if (cstart >= vl) return;
    const int kend   = (cstart + ck < vl) ? cstart + ck : vl;
    const int ntiles = (kend - cstart + BN - 1) / BN;

    const int B_ = gridDim.y;
    const int R  = B_ * Lq;

    const float* Qb = Q + ((size_t)b * Lq + q0) * DH;
    const float* Kb = K + ((size_t)b * Lk + cstart) * DH;
    const float* Vb = V + ((size_t)b * Lk + cstart) * DH;

    // ---- Q -> smem, pre-scaled, fp16 hi/lo split (exact q = qh + ql) ----
    {
        int r = t >> 1, h = t & 1;
        const float* qp = Qb + (size_t)r * DH + h * 32;
        float f[32];
        #pragma unroll
        for (int i = 0; i < 8; i++) *(float4*)(f + 4*i) = *(const float4*)(qp + 4*i);
        #pragma unroll
        for (int i = 0; i < 32; i++) f[i] *= 0.125f;   // 1/sqrt(64)
        #pragma unroll
        for (int cc = 0; cc < 4; cc++){
            uint4 hi, lo; splitH8(f + 8*cc, hi, lo);
            int off = r * SKB + (h*4 + cc) * 16;
            *(uint4*)(smem + SM_QHI + off) = hi;
            *(uint4*)(smem + SM_QLO + off) = lo;
        }
    }
    __syncthreads();

    // ---- Q A-fragments (registers for whole kernel) ----
    uint32_t qhi[4][4], qlo[4][4];
    {
        uint32_t rowoff = (uint32_t)(16*w + (ln & 15)) * SKB + (uint32_t)(ln >> 4) * 16;
        #pragma unroll
        for (int ks = 0; ks < 4; ks++){
            ldsm4(qhi[ks], sb + SM_QHI + rowoff + ks * 32);
            ldsm4(qlo[ks], sb + SM_QLO + rowoff + ks * 32);
        }
    }

    float oc[8][4];
    #pragma unroll
    for (int nt = 0; nt < 8; nt++)
        #pragma unroll
        for (int j = 0; j < 4; j++) oc[nt][j] = 0.f;
    float lsum0 = 0.f, lsum1 = 0.f;

    // ---- prefetch tile 0 ----
    const int r4 = t >> 2, qq = t & 3;
    float4 kf[4], vf[4];
    {
        const float* kp = Kb + (size_t)r4 * DH + qq * 16;
        const float* vp = Vb + (size_t)r4 * DH + qq * 16;
        #pragma unroll
        for (int i = 0; i < 4; i++){ kf[i] = *(const float4*)(kp + 4*i); vf[i] = *(const float4*)(vp + 4*i); }
    }

    for (int kt = 0; kt < ntiles; kt++){
        const int n0g = cstart + kt * BN;

        __syncthreads();   // prev tile's ldmatrix reads done
        // ---- store K/V tile as single fp16 (no split) ----
        {
            int off = r4 * SKB + qq * 32;
            float fk[8];
            uint4 u;
            *(float4*)(fk)   = kf[0]; *(float4*)(fk+4) = kf[1];
            cvtH8(fk, u); *(uint4*)(smem + SM_KH + off) = u;
            *(float4*)(fk)   = kf[2]; *(float4*)(fk+4) = kf[3];
            cvtH8(fk, u); *(uint4*)(smem + SM_KH + off + 16) = u;
            *(float4*)(fk)   = vf[0]; *(float4*)(fk+4) = vf[1];
            cvtH8(fk, u); *(uint4*)(smem + SM_VH + off) = u;
            *(float4*)(fk)   = vf[2]; *(float4*)(fk+4) = vf[3];
            cvtH8(fk, u); *(uint4*)(smem + SM_VH + off + 16) = u;
        }
        __syncthreads();

        // ---- prefetch next tile ----
        if (kt + 1 < ntiles){
            const float* kp = Kb + (size_t)((kt+1)*BN + r4) * DH + qq * 16;
            const float* vp = Vb + (size_t)((kt+1)*BN + r4) * DH + qq * 16;
            #pragma unroll
            for (int i = 0; i < 4; i++){ kf[i] = *(const float4*)(kp + 4*i); vf[i] = *(const float4*)(vp + 4*i); }
        }

        // ---- S = (qh + ql) * kh : 2 passes, kh read once ----
        float sc[8][4];
        #pragma unroll
        for (int nt = 0; nt < 8; nt++){
            #pragma unroll
            for (int j = 0; j < 4; j++) sc[nt][j] = 0.f;
            uint32_t kh[8];
            uint32_t base = (uint32_t)(8*nt + (ln & 7)) * SKB
                          + (uint32_t)((ln >> 3) & 1) * 16
                          + (uint32_t)(ln >> 4) * 32;
            ldsm4(kh + 0, sb + SM_KH + base);
            ldsm4(kh + 4, sb + SM_KH + base + 64);
            #pragma unroll
            for (int ks = 0; ks < 4; ks++){
                mma16816(sc[nt], qhi[ks], kh[2*ks], kh[2*ks+1]);
                mma16816(sc[nt], qlo[ks], kh[2*ks], kh[2*ks+1]);
            }
        }

        // ---- P = exp(S) with key-length mask; exact split p = ph + pl ----
        uint32_t phi[4][4], plo[4][4];
        #pragma unroll
        for (int nt = 0; nt < 8; nt++){
            int c0 = n0g + nt*8 + 2*tg;
            float e0 = (c0     < vl) ? __expf(sc[nt][0]) : 0.f;
            float e1 = (c0 + 1 < vl) ? __expf(sc[nt][1]) : 0.f;
            float e2 = (c0     < vl) ? __expf(sc[nt][2]) : 0.f;
            float e3 = (c0 + 1 < vl) ? __expf(sc[nt][3]) : 0.f;
            lsum0 += e0 + e1;
            lsum1 += e2 + e3;
            __half h0 = __float2half_rn(e0), h1 = __float2half_rn(e1);
            __half h2 = __float2half_rn(e2), h3 = __float2half_rn(e3);
            __half x0 = __float2half_rn(e0 - __half2float(h0));
            __half x1 = __float2half_rn(e1 - __half2float(h1));
            __half x2 = __float2half_rn(e2 - __half2float(h2));
            __half x3 = __float2half_rn(e3 - __half2float(h3));
            int j = nt >> 1, hf = (nt & 1) * 2;
            phi[j][hf + 0] = pkh(h0, h1); phi[j][hf + 1] = pkh(h2, h3);
            plo[j][hf + 0] = pkh(x0, x1); plo[j][hf + 1] = pkh(x2, x3);
        }

        // ---- O += (ph + pl) * vh : 2 passes, vh read once ----
        #pragma unroll
        for (int nt = 0; nt < 8; nt++){
            uint32_t vh[8];
            uint32_t base = (uint32_t)ln * SKB + (uint32_t)nt * 16;
            ldsm4t(vh + 0, sb + SM_VH + base);
            ldsm4t(vh + 4, sb + SM_VH + base + 32u * SKB);
            #pragma unroll
            for (int ks = 0; ks < 4; ks++){
                mma16816(oc[nt], phi[ks], vh[2*ks], vh[2*ks+1]);
                mma16816(oc[nt], plo[ks], vh[2*ks], vh[2*ks+1]);
            }
        }
    }

    // ---- reduce row sums across quads ----
    lsum0 += __shfl_xor_sync(0xffffffffu, lsum0, 1);
    lsum0 += __shfl_xor_sync(0xffffffffu, lsum0, 2);
    lsum1 += __shfl_xor_sync(0xffffffffu, lsum1, 1);
    lsum1 += __shfl_xor_sync(0xffffffffu, lsum1, 2);

    // ---- write unnormalized partials to scratch ----
    const int rg0 = b * Lq + q0 + 16*w + g;
    float* Op0 = g_Opart + ((size_t)c * R + rg0) * DH;
    float* Op1 = Op0 + (size_t)8 * DH;
    if (tg == 0){
        g_lpart[(size_t)c * R + rg0]     = lsum0;
        g_lpart[(size_t)c * R + rg0 + 8] = lsum1;
    }
    #pragma unroll
    for (int nt = 0; nt < 8; nt++){
        float2 a0, a1;
        a0.x = oc[nt][0]; a0.y = oc[nt][1];
        a1.x = oc[nt][2]; a1.y = oc[nt][3];
        *(float2*)(Op0 + nt*8 + 2*tg) = a0;
        *(float2*)(Op1 + nt*8 + 2*tg) = a1;
    }
}

// ---------------- Phase 2: combine chunk partials + normalize ----------------
__global__ __launch_bounds__(256, 8)
void fa_combine_kernel(const int* __restrict__ vlen, float* __restrict__ O,
                       int Lq, int Lk, int B, int ck)
{
    const int idx = blockIdx.x * blockDim.x + threadIdx.x;
    const int total = B * Lq * (DH / 4);
    if (idx >= total) return;

    const int rd = idx >> 4;
    const int d4 = idx & 15;
    const int b  = rd / Lq;
    const int R  = B * Lq;

    int vl = vlen[b];
    if (vl < 1) vl = 1;
    if (vl > Lk) vl = Lk;
    const int nact = (vl + ck - 1) / ck;

    float4 p[NCH_MAX];
    float  lp[NCH_MAX];
    #pragma unroll
    for (int c = 0; c < NCH_MAX; c++){
        p[c]  = *(const float4*)(g_Opart + ((size_t)c * R + rd) * DH + d4 * 4);
        lp[c] = g_lpart[(size_t)c * R + rd];
    }
    float4 acc = make_float4(0.f, 0.f, 0.f, 0.f);
    float l = 0.f;
    #pragma unroll
    for (int c = 0; c < NCH_MAX; c++){
        const bool v = (c < nact);
        acc.x += v ? p[c].x : 0.f;
        acc.y += v ? p[c].y : 0.f;
        acc.z += v ? p[c].z : 0.f;
        acc.w += v ? p[c].w : 0.f;
        l     += v ? lp[c]  : 0.f;
    }
    const float inv = 1.f / l;
    acc.x *= inv; acc.y *= inv; acc.z *= inv; acc.w *= inv;
    *(float4*)(O + (size_t)rd * DH + d4 * 4) = acc;
}

extern "C" void kernel_launch(void* const* d_in, const int* in_sizes, int n_in,
                              void* d_out, int out_size)
{
    const float* Q  = (const float*)d_in[0];
    const float* K  = (const float*)d_in[1];
    const float* V  = (const float*)d_in[2];
    const int*   vl = (const int*)d_in[3];
    float*       O  = (float*)d_out;

    const int B  = in_sizes[3];
    const int Lq = in_sizes[0] / (B * DH);
    const int Lk = in_sizes[1] / (B * DH);

    int ck = ((Lk + NCH_MAX * BN - 1) / (NCH_MAX * BN)) * BN;
    if (ck < BN) ck = BN;
    const int nch = (Lk + ck - 1) / ck;

    cudaFuncSetAttribute(fa_part_kernel,
                         cudaFuncAttributeMaxDynamicSharedMemorySize, SM_TOTAL);

    dim3 grid1(Lq / BM, B, nch);
    fa_part_kernel<<<grid1, 256, SM_TOTAL>>>(Q, K, V, vl, Lq, Lk, ck);

    const int total = B * Lq * (DH / 4);
    fa_combine_kernel<<<(total + 255) / 256, 256>>>(vl, O, Lq, Lk, B, ck);
}